// round 1
// baseline (speedup 1.0000x reference)
#include <cuda_runtime.h>
#include <math.h>

// MatchedFilterLoss fused kernel for GB300 (sm_103a)
// One block per (batch, channel) row: 512 blocks x 256 threads.
//
// Pipeline per row (2048 samples):
//  1. center x_hat (min/max scale to [-1,1])
//  2. shifted Pearson corr over 103 shifts -> max -> base loss
//  3. one complex 2048-pt FFT computes rfft of both signals (z = xh + i*y)
//  4. chisq statistic over masked bins [32..1024], final loss

#define NTH 256

__global__ __launch_bounds__(256)
void mfl_kernel(const float* __restrict__ xhat_g,
                const float* __restrict__ x_g,
                float* __restrict__ out)
{
    // padded centered x_hat: [0..50]=0 | 2048 data | tail zeros
    __shared__ float xhp[2176];
    __shared__ float xim[2048];          // x row (also FFT imag part)
    __shared__ float buf[2048];          // yc -> twiddles -> si(0..992) / si2(1024..2016)
    __shared__ float P1[52], P2[52], Q1[52], Q2[52];
    __shared__ float red[32];
    __shared__ float wmax[8];
    __shared__ float s_mn, s_mx, s_my, s_T1, s_T2, s_Vy, s_lossbase;
    __shared__ float s_total, s_total2;
    __shared__ int   s_edges[17];

    const int tid  = threadIdx.x;
    const int lane = tid & 31;
    const int wid  = tid >> 5;
    const int row  = blockIdx.x;

    const float* xh_in = xhat_g + (size_t)row * 2048;
    const float* x_in  = x_g    + (size_t)row * 2048;
    float* px = xhp + 51;   // logical xh[0..2047]; px[-51..-1] and px[2048..] are zero

    // ---- 1. load + zero pads -------------------------------------------
    for (int i = tid; i < 2048; i += NTH) {
        px[i]  = xh_in[i];
        xim[i] = x_in[i];
    }
    for (int i = tid; i < 51; i += NTH) xhp[i] = 0.f;
    for (int i = 2099 + tid; i < 2176; i += NTH) xhp[i] = 0.f;
    __syncthreads();

    // ---- 2. min/max of x_hat, mean of x --------------------------------
    {
        float mn = 1e30f, mx = -1e30f, sy = 0.f;
        for (int i = tid; i < 2048; i += NTH) {
            float v = px[i];
            mn = fminf(mn, v); mx = fmaxf(mx, v);
            sy += xim[i];
        }
        for (int off = 16; off; off >>= 1) {
            mn = fminf(mn, __shfl_xor_sync(0xffffffffu, mn, off));
            mx = fmaxf(mx, __shfl_xor_sync(0xffffffffu, mx, off));
            sy += __shfl_xor_sync(0xffffffffu, sy, off);
        }
        if (lane == 0) { red[wid] = mn; red[8 + wid] = mx; red[16 + wid] = sy; }
        __syncthreads();
        if (tid == 0) {
            float a = red[0], b = red[8], c = red[16];
            for (int w = 1; w < 8; w++) {
                a = fminf(a, red[w]); b = fmaxf(b, red[8 + w]); c += red[16 + w];
            }
            s_mn = a; s_mx = b; s_my = c * (1.0f / 2048.0f);
        }
        __syncthreads();
    }

    // ---- 3. center x_hat, yc = x - mean --------------------------------
    {
        float mn = s_mn, inv = 1.0f / (s_mx - s_mn), my = s_my;
        for (int i = tid; i < 2048; i += NTH) {
            float v = px[i];
            px[i] = 2.0f * (v - mn) * inv - 1.0f;
            buf[i] = xim[i] - my;
        }
        __syncthreads();
    }

    // ---- 4. totals + head/tail prefix sums -----------------------------
    {
        float t1 = 0.f, t2 = 0.f, vy = 0.f;
        for (int i = tid; i < 2048; i += NTH) {
            float a = px[i]; t1 += a; t2 += a * a;
            float b = buf[i]; vy += b * b;
        }
        for (int off = 16; off; off >>= 1) {
            t1 += __shfl_xor_sync(0xffffffffu, t1, off);
            t2 += __shfl_xor_sync(0xffffffffu, t2, off);
            vy += __shfl_xor_sync(0xffffffffu, vy, off);
        }
        if (lane == 0) { red[wid] = t1; red[8 + wid] = t2; red[16 + wid] = vy; }

        // head / tail prefix sums for window mean/variance corrections
        if (tid < 52) {
            float a = 0.f, b = 0.f;
            for (int j = 0; j < tid; j++) { float v = px[j]; a += v; b += v * v; }
            P1[tid] = a; P2[tid] = b;
        } else if (tid >= 64 && tid < 116) {
            int m = tid - 64;
            float a = 0.f, b = 0.f;
            for (int j = 0; j < m; j++) { float v = px[2047 - j]; a += v; b += v * v; }
            Q1[m] = a; Q2[m] = b;
        }
        __syncthreads();
        if (tid == 0) {
            float a = red[0], b = red[8], c = red[16];
            for (int w = 1; w < 8; w++) { a += red[w]; b += red[8 + w]; c += red[16 + w]; }
            s_T1 = a; s_T2 = b; s_Vy = c;
        }
        __syncthreads();
    }

    // ---- 5. shifted Pearson: warp handles 13 consecutive shifts --------
    {
        float acc[13];
#pragma unroll
        for (int k = 0; k < 13; k++) acc[k] = 0.f;
        const int wbase = wid * 13;        // window indices [wbase, wbase+13)
        const int dbase = wbase - 51;      // shift d = w - 51

        for (int c = 0; c < 8; c++) {
            const int j0 = c * 256 + lane * 8;
            float ycr[8], xr[8];
#pragma unroll
            for (int r = 0; r < 8; r++) ycr[r] = buf[j0 + r];
#pragma unroll
            for (int r = 0; r < 8; r++) xr[r] = px[j0 + dbase + r];
#pragma unroll
            for (int k = 0; k < 13; k++) {
                if (wbase + k < 103) {
#pragma unroll
                    for (int r = 0; r < 8; r++) acc[k] += xr[r] * ycr[r];
                }
#pragma unroll
                for (int r = 0; r < 7; r++) xr[r] = xr[r + 1];
                xr[7] = px[j0 + dbase + k + 8];
            }
        }

#pragma unroll
        for (int k = 0; k < 13; k++) {
            float v = acc[k];
            for (int off = 16; off; off >>= 1)
                v += __shfl_xor_sync(0xffffffffu, v, off);
            acc[k] = v;
        }
        if (lane == 0) {
            float best = -2.f;
            const float T1 = s_T1, T2 = s_T2, Vy = s_Vy;
            for (int k = 0; k < 13; k++) {
                int w = wbase + k;
                if (w >= 103) break;
                int d = w - 51;
                float S1, S2v;
                if (d >= 0) { S1 = T1 - P1[d];  S2v = T2 - P2[d]; }
                else        { S1 = T1 - Q1[-d]; S2v = T2 - Q2[-d]; }
                float varx = S2v - S1 * S1 * (1.0f / 2048.0f);
                float corr = acc[k] / sqrtf(varx * Vy);
                best = fmaxf(best, corr);
            }
            wmax[wid] = best;
        }
        __syncthreads();
        if (tid == 0) {
            float b = wmax[0];
            for (int w = 1; w < 8; w++) b = fmaxf(b, wmax[w]);
            s_lossbase = (1.0f - b) / (1.0f + b);
        }
        __syncthreads();
    }

    // ---- 6. twiddle table: buf[k]=cos, buf[1024+k]=sin of -2*pi*k/2048 -
    for (int k = tid; k < 1024; k += NTH) {
        float s, c;
        sincospif(-(float)k * (1.0f / 1024.0f), &s, &c);
        buf[k] = c; buf[1024 + k] = s;
    }
    __syncthreads();

    // ---- 7. bit reversal (z = xh + i*y) --------------------------------
    for (int i = tid; i < 2048; i += NTH) {
        int j = __brev((unsigned)i) >> 21;
        if (i < j) {
            float tr = px[i];  px[i]  = px[j];  px[j]  = tr;
            float ti = xim[i]; xim[i] = xim[j]; xim[j] = ti;
        }
    }
    __syncthreads();

    // ---- 8. radix-2 DIT FFT, 11 stages ---------------------------------
    {
        int mult = 1024;
        for (int len = 1; len < 2048; len <<= 1) {
            for (int t = tid; t < 1024; t += NTH) {
                int pos = t & (len - 1);
                int i0  = 2 * t - pos;
                int i1  = i0 + len;
                int ti  = pos * mult;
                float wr = buf[ti], wi2 = buf[1024 + ti];
                float ar = px[i0],  ai = xim[i0];
                float br = px[i1],  bi = xim[i1];
                float vr = br * wr - bi * wi2;
                float vi = br * wi2 + bi * wr;
                px[i0]  = ar + vr; xim[i0] = ai + vi;
                px[i1]  = ar - vr; xim[i1] = ai - vi;
            }
            mult >>= 1;
            __syncthreads();
        }
    }

    // ---- 9. untangle H,S on masked bins, build integrands --------------
    for (int k = 32 + tid; k <= 1024; k += NTH) {
        int nk = 2048 - k;
        float zr = px[k],  zi = xim[k];
        float wr = px[nk], wi = xim[nk];
        const float sc = 0.5f / 2048.0f;               // untangle /2 and rfft /SAMPLE_RATE
        float hr = (zr + wr) * sc, hi = (zi - wi) * sc; // H = rfft(x_hat)/2048
        float sr = (zi + wi) * sc, si = (wr - zr) * sc; // S = rfft(x)/2048
        float a  = 4.0f * (hr * hr + hi * hi);          // |4 H conj(H)|
        float pr = hr * sr + hi * si;                   // H * conj(S)
        float pi = hi * sr - hr * si;
        float cm = 4.0f * sqrtf(pr * pr + pi * pi);     // |4 H conj(S)|
        buf[k - 32]        = a;
        buf[1024 + k - 32] = cm;
    }
    __syncthreads();

    // ---- 10. cumsums (serial, fp32 like reference) ---------------------
    if (tid == 0) {
        float s = 0.f;
        for (int j = 0; j < 993; j++) { s += buf[j]; buf[j] = s; }
        s_total = s;
        float inv_st = 1.0f / sqrtf(s);     // qtilde = H / sqrt(total)
        float s2 = 0.f;
        for (int j = 0; j < 993; j++) { s2 += buf[1024 + j] * inv_st; buf[1024 + j] = s2; }
        s_total2 = s2;
    }
    __syncthreads();

    // ---- 11. edges: searchsorted(si, k/16 * total, 'right'), clip ------
    if (tid < 17) {
        float v = ((float)tid * (1.0f / 16.0f)) * s_total;
        int lo = 0, hi = 993;
        while (lo < hi) {
            int mid = (lo + hi) >> 1;
            if (buf[mid] <= v) lo = mid + 1; else hi = mid;
        }
        if (lo > 992) lo = 992;
        s_edges[tid] = lo;
    }
    __syncthreads();

    // ---- 12. chisq + final loss ----------------------------------------
    if (tid == 0) {
        float mean = s_total2 * (1.0f / 16.0f);
        float ssum = 0.f;
        for (int k = 0; k < 16; k++) {
            float r = buf[1024 + s_edges[k + 1]];
            float l = buf[1024 + s_edges[k]];
            float d = (r - l) - mean;
            ssum += d * d;
        }
        float chisq = 16.0f * ssum * (1.0f / 15.0f);
        float c3 = chisq * chisq * chisq;
        float loss = s_lossbase * powf(1.0f + c3, 1.0f / 6.0f);
        out[row] = loss;
    }
}

extern "C" void kernel_launch(void* const* d_in, const int* in_sizes, int n_in,
                              void* d_out, int out_size)
{
    const float* x_hat = (const float*)d_in[0];
    const float* x     = (const float*)d_in[1];
    float* out = (float*)d_out;
    // 256 batches * 2 channels = 512 rows
    mfl_kernel<<<512, 256>>>(x_hat, x, out);
}

// round 2
// speedup vs baseline: 2.0203x; 2.0203x over previous
#include <cuda_runtime.h>
#include <math.h>

// MatchedFilterLoss fused kernel for GB300 (sm_103a)
// 512 blocks (one per batch*channel row) x 256 threads.

#define NTH 256

__device__ float2 d_tw[2048];   // w_2048^t = exp(-2*pi*i*t/2048)

__global__ void tw_init_kernel()
{
    int t = blockIdx.x * blockDim.x + threadIdx.x;
    if (t < 2048) {
        float s, c;
        sincospif(-(float)t * (1.0f / 1024.0f), &s, &c);
        d_tw[t] = make_float2(c, s);
    }
}

// storage position of natural frequency k after radix-[4,4,4,4,4,2] DIF
__device__ __forceinline__ int fpos(int k)
{
    return ((k & 3) << 9) | (((k >> 2) & 3) << 7) | (((k >> 4) & 3) << 5)
         | (((k >> 6) & 3) << 3) | (((k >> 8) & 3) << 1) | (k >> 10);
}

__device__ __forceinline__ float2 cmul(float ar, float ai, float2 w)
{
    return make_float2(ar * w.x - ai * w.y, ar * w.y + ai * w.x);
}

// Pearson inner kernel with compile-time alignment offset
#define PKER(OFF)                                               \
    _Pragma("unroll")                                           \
    for (int k = 0; k < 13; k++) {                              \
        _Pragma("unroll")                                       \
        for (int r = 0; r < 8; r++)                             \
            acc[k] += xw[(OFF) + k + r] * ycr[r];               \
    }

__global__ __launch_bounds__(256, 4)
void mfl_kernel(const float* __restrict__ xhat_g,
                const float* __restrict__ x_g,
                float* __restrict__ out)
{
    __shared__ float xhp[2184];      // px = xhp+52: [0..51]=0 | 2048 centered xh | zeros
    __shared__ float xv[2048];       // original x
    __shared__ float yc[2048];       // x - mean; later integrand cumsums (a:0..992, cm:1024..2016)
    __shared__ float2 z[2048];       // FFT workspace
    __shared__ float P1[52], P2[52], Q1[52], Q2[52];
    __shared__ float red[24];
    __shared__ float wA[8], wB[8];
    __shared__ float wmax[8];
    __shared__ float s_mn, s_mx, s_my, s_T1, s_T2, s_Vy, s_lossbase;
    __shared__ float s_total, s_tot2raw, s_inv;
    __shared__ int   s_edges[17];

    const int tid  = threadIdx.x;
    const int lane = tid & 31;
    const int wid  = tid >> 5;
    const int row  = blockIdx.x;

    const float4* xh4 = (const float4*)(xhat_g + (size_t)row * 2048);
    const float4* x4g = (const float4*)(x_g    + (size_t)row * 2048);
    float* px = xhp + 52;

    // ---- 1. vector load + first-pass stats (min/max of xh, sum of x) ----
    {
        float mn = 1e30f, mx = -1e30f, sy = 0.f;
#pragma unroll
        for (int c = 0; c < 2; c++) {
            int i = tid + c * 256;               // float4 index
            float4 h = xh4[i];
            float4 v = x4g[i];
            ((float4*)px)[i]  = h;               // px 16B aligned (offset 52 floats)
            ((float4*)xv)[i]  = v;
            mn = fminf(mn, fminf(fminf(h.x, h.y), fminf(h.z, h.w)));
            mx = fmaxf(mx, fmaxf(fmaxf(h.x, h.y), fmaxf(h.z, h.w)));
            sy += v.x + v.y + v.z + v.w;
        }
        // zero pads
        if (tid < 52) xhp[tid] = 0.f;
        if (tid >= 64 && tid < 64 + 84) xhp[2100 + (tid - 64)] = 0.f;

        for (int off = 16; off; off >>= 1) {
            mn = fminf(mn, __shfl_xor_sync(0xffffffffu, mn, off));
            mx = fmaxf(mx, __shfl_xor_sync(0xffffffffu, mx, off));
            sy += __shfl_xor_sync(0xffffffffu, sy, off);
        }
        if (lane == 0) { red[wid] = mn; red[8 + wid] = mx; red[16 + wid] = sy; }
        __syncthreads();
        if (tid == 0) {
            float a = red[0], b = red[8], c = red[16];
            for (int w = 1; w < 8; w++) {
                a = fminf(a, red[w]); b = fmaxf(b, red[8 + w]); c += red[16 + w];
            }
            s_mn = a; s_mx = b; s_my = c * (1.0f / 2048.0f);
        }
        __syncthreads();
    }

    // ---- 2. center xh, yc = x - mean, accumulate totals -----------------
    {
        float mn = s_mn, inv = 1.0f / (s_mx - s_mn), my = s_my;
        float t1 = 0.f, t2 = 0.f, vy = 0.f;
#pragma unroll
        for (int c = 0; c < 2; c++) {
            int i = tid + c * 256;
            float4 h = ((float4*)px)[i];
            float4 v = ((float4*)xv)[i];
            h.x = 2.0f * (h.x - mn) * inv - 1.0f;
            h.y = 2.0f * (h.y - mn) * inv - 1.0f;
            h.z = 2.0f * (h.z - mn) * inv - 1.0f;
            h.w = 2.0f * (h.w - mn) * inv - 1.0f;
            float4 y = make_float4(v.x - my, v.y - my, v.z - my, v.w - my);
            ((float4*)px)[i] = h;
            ((float4*)yc)[i] = y;
            t1 += h.x + h.y + h.z + h.w;
            t2 += h.x * h.x + h.y * h.y + h.z * h.z + h.w * h.w;
            vy += y.x * y.x + y.y * y.y + y.z * y.z + y.w * y.w;
        }
        for (int off = 16; off; off >>= 1) {
            t1 += __shfl_xor_sync(0xffffffffu, t1, off);
            t2 += __shfl_xor_sync(0xffffffffu, t2, off);
            vy += __shfl_xor_sync(0xffffffffu, vy, off);
        }
        if (lane == 0) { red[wid] = t1; red[8 + wid] = t2; red[16 + wid] = vy; }
        __syncthreads();

        // head / tail prefix sums of centered xh (for window mean/var corrections)
        if (tid < 52) {
            float a = 0.f, b = 0.f;
            for (int j = 0; j < tid; j++) { float u = px[j]; a += u; b += u * u; }
            P1[tid] = a; P2[tid] = b;
        } else if (tid >= 64 && tid < 116) {
            int m = tid - 64;
            float a = 0.f, b = 0.f;
            for (int j = 0; j < m; j++) { float u = px[2047 - j]; a += u; b += u * u; }
            Q1[m] = a; Q2[m] = b;
        }
        if (tid == 128) {
            float a = red[0], b = red[8], c = red[16];
            for (int w = 1; w < 8; w++) { a += red[w]; b += red[8 + w]; c += red[16 + w]; }
            s_T1 = a; s_T2 = b; s_Vy = c;
        }
        __syncthreads();
    }

    // ---- 3. shifted Pearson: warp w handles shifts [13w, 13w+13) --------
    {
        float acc[13];
#pragma unroll
        for (int k = 0; k < 13; k++) acc[k] = 0.f;
        const int wbase = wid * 13;
        const int dbase = wbase - 51;
        const int off   = dbase & 3;       // warp-uniform
        const int ab0   = dbase - off;     // multiple of 4

        for (int c = 0; c < 8; c++) {
            const int j0 = c * 256 + lane * 8;
            float4 y0 = *(const float4*)&yc[j0];
            float4 y1 = *(const float4*)&yc[j0 + 4];
            float ycr[8] = { y0.x, y0.y, y0.z, y0.w, y1.x, y1.y, y1.z, y1.w };

            const float4* xp4 = (const float4*)&px[j0 + ab0];   // 16B aligned
            float4 a0 = xp4[0], a1 = xp4[1], a2 = xp4[2];
            float4 a3 = xp4[3], a4 = xp4[4], a5 = xp4[5];
            float xw[24] = { a0.x,a0.y,a0.z,a0.w, a1.x,a1.y,a1.z,a1.w,
                             a2.x,a2.y,a2.z,a2.w, a3.x,a3.y,a3.z,a3.w,
                             a4.x,a4.y,a4.z,a4.w, a5.x,a5.y,a5.z,a5.w };
            switch (off) {
                case 0: PKER(0); break;
                case 1: PKER(1); break;
                case 2: PKER(2); break;
                default: PKER(3); break;
            }
        }

#pragma unroll
        for (int k = 0; k < 13; k++) {
            float v = acc[k];
            for (int o = 16; o; o >>= 1)
                v += __shfl_xor_sync(0xffffffffu, v, o);
            acc[k] = v;
        }
        if (lane == 0) {
            float best = -2.f;
            const float T1 = s_T1, T2 = s_T2, Vy = s_Vy;
            for (int k = 0; k < 13; k++) {
                int w = wbase + k;
                if (w >= 103) break;
                int d = w - 51;
                float S1, S2v;
                if (d >= 0) { S1 = T1 - P1[d];  S2v = T2 - P2[d]; }
                else        { S1 = T1 - Q1[-d]; S2v = T2 - Q2[-d]; }
                float varx = S2v - S1 * S1 * (1.0f / 2048.0f);
                float corr = acc[k] / sqrtf(varx * Vy);
                best = fmaxf(best, corr);
            }
            wmax[wid] = best;
        }
        __syncthreads();
        if (tid == 0) {
            float b = wmax[0];
            for (int w = 1; w < 8; w++) b = fmaxf(b, wmax[w]);
            s_lossbase = (1.0f - b) / (1.0f + b);
        }
    }

    // ---- 4. pack z = centered_xh + i * x --------------------------------
    for (int i = tid; i < 2048; i += NTH)
        z[i] = make_float2(px[i], xv[i]);
    __syncthreads();

    // ---- 5. radix-4 DIF FFT (5 stages) + radix-2 final ------------------
#pragma unroll
    for (int s = 0; s < 5; s++) {
        const int lq   = 9 - 2 * s;          // log2(q), q = n/4
        const int q    = 1 << lq;
        const int mult = 1 << (2 * s);       // 2048/n
#pragma unroll
        for (int it = 0; it < 2; it++) {
            int b    = tid + it * 256;       // 512 butterflies
            int j    = b & (q - 1);
            int base = ((b >> lq) << (lq + 2)) + j;
            float2 x0 = z[base], x1 = z[base + q];
            float2 x2 = z[base + 2 * q], x3 = z[base + 3 * q];
            float t0r = x0.x + x2.x, t0i = x0.y + x2.y;
            float t1r = x1.x + x3.x, t1i = x1.y + x3.y;
            float t2r = x0.x - x2.x, t2i = x0.y - x2.y;
            float t3r = x1.y - x3.y, t3i = x3.x - x1.x;   // -i*(x1-x3)
            z[base] = make_float2(t0r + t1r, t0i + t1i);
            int e1 = j * mult;
            float2 w1 = __ldg(&d_tw[e1]);
            float2 w2 = __ldg(&d_tw[2 * e1]);
            float2 w3 = __ldg(&d_tw[3 * e1]);
            z[base + q]     = cmul(t2r + t3r, t2i + t3i, w1);
            z[base + 2 * q] = cmul(t0r - t1r, t0i - t1i, w2);
            z[base + 3 * q] = cmul(t2r - t3r, t2i - t3i, w3);
        }
        __syncthreads();
    }
#pragma unroll
    for (int it = 0; it < 4; it++) {
        int b = tid + it * 256;              // 1024 pairs
        float2 a = z[2 * b], c = z[2 * b + 1];
        z[2 * b]     = make_float2(a.x + c.x, a.y + c.y);
        z[2 * b + 1] = make_float2(a.x - c.x, a.y - c.y);
    }
    __syncthreads();

    // ---- 6. untangle H,S on masked bins, build integrands ---------------
    for (int k = 32 + tid; k <= 1024; k += NTH) {
        float2 Z = z[fpos(k)];
        float2 W = z[fpos(2048 - k)];
        const float sc = 0.5f / 2048.0f;
        float hr = (Z.x + W.x) * sc, hi = (Z.y - W.y) * sc;   // rfft(xh)/2048
        float sr = (Z.y + W.y) * sc, si = (W.x - Z.x) * sc;   // rfft(x)/2048
        float a  = 4.0f * (hr * hr + hi * hi);
        float pr = hr * sr + hi * si;
        float pi = hi * sr - hr * si;
        float cm = 4.0f * sqrtf(pr * pr + pi * pi);
        yc[k - 32]        = a;
        yc[1024 + k - 32] = cm;
    }
    __syncthreads();

    // ---- 7. dual parallel inclusive scan over 993 elements --------------
    {
        const int i0 = tid * 4;
        float av[4], bv[4];
#pragma unroll
        for (int u = 0; u < 4; u++) {
            int i = i0 + u;
            av[u] = (i < 993) ? yc[i] : 0.f;
            bv[u] = (i < 993) ? yc[1024 + i] : 0.f;
        }
        av[1] += av[0]; av[2] += av[1]; av[3] += av[2];
        bv[1] += bv[0]; bv[2] += bv[1]; bv[3] += bv[2];
        float la = av[3], lb = bv[3];
        float ainc = la, binc = lb;
#pragma unroll
        for (int o = 1; o < 32; o <<= 1) {
            float va = __shfl_up_sync(0xffffffffu, ainc, o);
            float vb = __shfl_up_sync(0xffffffffu, binc, o);
            if (lane >= o) { ainc += va; binc += vb; }
        }
        if (lane == 31) { wA[wid] = ainc; wB[wid] = binc; }
        __syncthreads();
        float baseA = 0.f, baseB = 0.f;
        for (int w = 0; w < wid; w++) { baseA += wA[w]; baseB += wB[w]; }
        float aex = baseA + ainc - la;
        float bex = baseB + binc - lb;
#pragma unroll
        for (int u = 0; u < 4; u++) {
            int i = i0 + u;
            if (i < 993) {
                yc[i]        = aex + av[u];
                yc[1024 + i] = bex + bv[u];
            }
        }
        __syncthreads();
        if (tid == 0) {
            float tot = yc[992];
            s_total   = tot;
            s_inv     = 1.0f / sqrtf(tot);
            s_tot2raw = yc[1024 + 992];
        }
        __syncthreads();
    }

    // ---- 8. edges: searchsorted(si, k/16*total, 'right'), clip ----------
    if (tid < 17) {
        float v = ((float)tid * (1.0f / 16.0f)) * s_total;
        int lo = 0, hi = 993;
        while (lo < hi) {
            int mid = (lo + hi) >> 1;
            if (yc[mid] <= v) lo = mid + 1; else hi = mid;
        }
        if (lo > 992) lo = 992;
        s_edges[tid] = lo;
    }
    __syncthreads();

    // ---- 9. chisq + final loss ------------------------------------------
    if (tid == 0) {
        float inv = s_inv;
        float total2 = s_tot2raw * inv;
        float mean = total2 * (1.0f / 16.0f);
        float ssum = 0.f;
        for (int k = 0; k < 16; k++) {
            float r = yc[1024 + s_edges[k + 1]] * inv;
            float l = yc[1024 + s_edges[k]] * inv;
            float d = (r - l) - mean;
            ssum += d * d;
        }
        float chisq = 16.0f * ssum * (1.0f / 15.0f);
        float c3 = chisq * chisq * chisq;
        out[row] = s_lossbase * powf(1.0f + c3, 1.0f / 6.0f);
    }
}

extern "C" void kernel_launch(void* const* d_in, const int* in_sizes, int n_in,
                              void* d_out, int out_size)
{
    const float* x_hat = (const float*)d_in[0];
    const float* x     = (const float*)d_in[1];
    float* out = (float*)d_out;
    tw_init_kernel<<<8, 256>>>();
    mfl_kernel<<<512, 256>>>(x_hat, x, out);
}

// round 3
// speedup vs baseline: 2.1686x; 1.0734x over previous
#include <cuda_runtime.h>
#include <math.h>

// MatchedFilterLoss fused kernel for GB300 (sm_103a)
// 512 blocks (one per batch*channel row) x 256 threads.
// Pearson cross-correlation is computed SPECTRALLY: the H*conj(S) product
// needed for chisq doubles as the correlation spectrum; a second FFT pass
// plus O(51) wraparound corrections replaces the 211K-FMA direct Pearson.

#define NTH 256

__device__ float2 d_tw[2048];   // w_2048^t = exp(-2*pi*i*t/2048)

__global__ void tw_init_kernel()
{
    int t = blockIdx.x * blockDim.x + threadIdx.x;
    if (t < 2048) {
        float s, c;
        sincospif(-(float)t * (1.0f / 1024.0f), &s, &c);
        d_tw[t] = make_float2(c, s);
    }
}

// storage position of natural frequency k after radix-[4,4,4,4,4,2] DIF
__device__ __forceinline__ int fpos(int k)
{
    return ((k & 3) << 9) | (((k >> 2) & 3) << 7) | (((k >> 4) & 3) << 5)
         | (((k >> 6) & 3) << 3) | (((k >> 8) & 3) << 1) | (k >> 10);
}

__device__ __forceinline__ float2 cmul(float ar, float ai, float2 w)
{
    return make_float2(ar * w.x - ai * w.y, ar * w.y + ai * w.x);
}

// in-place 2048-pt complex DIF FFT (natural in -> digit-reversed out).
// Ends with a __syncthreads().
__device__ __forceinline__ void fft2048(float2* z, int tid)
{
#pragma unroll
    for (int s = 0; s < 5; s++) {
        const int lq   = 9 - 2 * s;          // log2(q), q = n/4
        const int q    = 1 << lq;
        const int mult = 1 << (2 * s);       // 2048/n
#pragma unroll
        for (int it = 0; it < 2; it++) {
            int b    = tid + it * 256;       // 512 butterflies
            int j    = b & (q - 1);
            int base = ((b >> lq) << (lq + 2)) + j;
            float2 x0 = z[base], x1 = z[base + q];
            float2 x2 = z[base + 2 * q], x3 = z[base + 3 * q];
            float t0r = x0.x + x2.x, t0i = x0.y + x2.y;
            float t1r = x1.x + x3.x, t1i = x1.y + x3.y;
            float t2r = x0.x - x2.x, t2i = x0.y - x2.y;
            float t3r = x1.y - x3.y, t3i = x3.x - x1.x;   // -i*(x1-x3)
            z[base] = make_float2(t0r + t1r, t0i + t1i);
            int e1 = j * mult;
            float2 w1 = __ldg(&d_tw[e1]);
            float2 w2 = __ldg(&d_tw[2 * e1]);
            float2 w3 = __ldg(&d_tw[3 * e1]);
            z[base + q]     = cmul(t2r + t3r, t2i + t3i, w1);
            z[base + 2 * q] = cmul(t0r - t1r, t0i - t1i, w2);
            z[base + 3 * q] = cmul(t2r - t3r, t2i - t3i, w3);
        }
        __syncthreads();
    }
#pragma unroll
    for (int it = 0; it < 4; it++) {
        int b = tid + it * 256;              // 1024 radix-2 pairs
        float2 a = z[2 * b], c = z[2 * b + 1];
        z[2 * b]     = make_float2(a.x + c.x, a.y + c.y);
        z[2 * b + 1] = make_float2(a.x - c.x, a.y - c.y);
    }
    __syncthreads();
}

__global__ __launch_bounds__(256, 4)
void mfl_kernel(const float* __restrict__ xhat_g,
                const float* __restrict__ x_g,
                float* __restrict__ out)
{
    __shared__ float xh[2048];       // centered x_hat (alive until corr phase)
    __shared__ float xv[2048];       // x; after FFT#1: integrand planes a|cm
    __shared__ float yc[2048];       // x - mean (alive until corr phase)
    __shared__ float2 z[2048];       // FFT workspace (both FFTs)
    __shared__ float P1[52], P2[52], Q1[52], Q2[52];
    __shared__ float red[24];
    __shared__ float wA[8], wB[8];
    __shared__ float wmax[4];
    __shared__ float s_mn, s_mx, s_my, s_T1, s_T2, s_Vy, s_lossbase;
    __shared__ float s_total, s_tot2raw, s_inv;
    __shared__ int   s_edges[17];

    const int tid  = threadIdx.x;
    const int lane = tid & 31;
    const int wid  = tid >> 5;
    const int row  = blockIdx.x;

    const float4* xh4 = (const float4*)(xhat_g + (size_t)row * 2048);
    const float4* x4g = (const float4*)(x_g    + (size_t)row * 2048);

    // ---- 1. vector load + first-pass stats (min/max of xh, sum of x) ----
    {
        float mn = 1e30f, mx = -1e30f, sy = 0.f;
#pragma unroll
        for (int c = 0; c < 2; c++) {
            int i = tid + c * 256;               // float4 index
            float4 h = xh4[i];
            float4 v = x4g[i];
            ((float4*)xh)[i] = h;
            ((float4*)xv)[i] = v;
            mn = fminf(mn, fminf(fminf(h.x, h.y), fminf(h.z, h.w)));
            mx = fmaxf(mx, fmaxf(fmaxf(h.x, h.y), fmaxf(h.z, h.w)));
            sy += v.x + v.y + v.z + v.w;
        }
        for (int off = 16; off; off >>= 1) {
            mn = fminf(mn, __shfl_xor_sync(0xffffffffu, mn, off));
            mx = fmaxf(mx, __shfl_xor_sync(0xffffffffu, mx, off));
            sy += __shfl_xor_sync(0xffffffffu, sy, off);
        }
        if (lane == 0) { red[wid] = mn; red[8 + wid] = mx; red[16 + wid] = sy; }
        __syncthreads();
        if (tid == 0) {
            float a = red[0], b = red[8], c = red[16];
            for (int w = 1; w < 8; w++) {
                a = fminf(a, red[w]); b = fmaxf(b, red[8 + w]); c += red[16 + w];
            }
            s_mn = a; s_mx = b; s_my = c * (1.0f / 2048.0f);
        }
        __syncthreads();
    }

    // ---- 2. center xh, yc = x - mean, totals, head/tail prefix sums -----
    {
        float mn = s_mn, inv = 1.0f / (s_mx - s_mn), my = s_my;
        float t1 = 0.f, t2 = 0.f, vy = 0.f;
#pragma unroll
        for (int c = 0; c < 2; c++) {
            int i = tid + c * 256;
            float4 h = ((float4*)xh)[i];
            float4 v = ((float4*)xv)[i];
            h.x = 2.0f * (h.x - mn) * inv - 1.0f;
            h.y = 2.0f * (h.y - mn) * inv - 1.0f;
            h.z = 2.0f * (h.z - mn) * inv - 1.0f;
            h.w = 2.0f * (h.w - mn) * inv - 1.0f;
            float4 y = make_float4(v.x - my, v.y - my, v.z - my, v.w - my);
            ((float4*)xh)[i] = h;
            ((float4*)yc)[i] = y;
            t1 += h.x + h.y + h.z + h.w;
            t2 += h.x * h.x + h.y * h.y + h.z * h.z + h.w * h.w;
            vy += y.x * y.x + y.y * y.y + y.z * y.z + y.w * y.w;
        }
        for (int off = 16; off; off >>= 1) {
            t1 += __shfl_xor_sync(0xffffffffu, t1, off);
            t2 += __shfl_xor_sync(0xffffffffu, t2, off);
            vy += __shfl_xor_sync(0xffffffffu, vy, off);
        }
        if (lane == 0) { red[wid] = t1; red[8 + wid] = t2; red[16 + wid] = vy; }
        __syncthreads();

        // head / tail prefix sums of centered xh (window mean/var corrections)
        if (tid < 52) {
            float a = 0.f, b = 0.f;
            for (int j = 0; j < tid; j++) { float u = xh[j]; a += u; b += u * u; }
            P1[tid] = a; P2[tid] = b;
        } else if (tid >= 64 && tid < 116) {
            int m = tid - 64;
            float a = 0.f, b = 0.f;
            for (int j = 0; j < m; j++) { float u = xh[2047 - j]; a += u; b += u * u; }
            Q1[m] = a; Q2[m] = b;
        }
        if (tid == 128) {
            float a = red[0], b = red[8], c = red[16];
            for (int w = 1; w < 8; w++) { a += red[w]; b += red[8 + w]; c += red[16 + w]; }
            s_T1 = a; s_T2 = b; s_Vy = c;
        }

        // pack z = centered_xh + i * x (same sync covers it)
#pragma unroll
        for (int c = 0; c < 8; c++) {
            int i = tid + c * 256;
            z[i] = make_float2(xh[i], xv[i]);
        }
        __syncthreads();
    }

    // ---- 3. FFT #1 ------------------------------------------------------
    fft2048(z, tid);

    // ---- 4. untangle all bins: chisq integrands + corr spectrum G -------
    // H = rfft(xh)/2048, S = rfft(x)/2048, P = H*conj(S).
    // G[k] = conj(P[k]) (k=0..1024, G[0]=0), G[2048-k] = P[k]  (Hermitian).
    // Then r_circ[d] = 2048 * Re( FFT(G)[d] ).
    {
        float2 Gk[4];
#pragma unroll
        for (int it = 0; it < 4; it++) {
            int k = 1 + tid + it * 256;          // 1..1024
            float2 Z = z[fpos(k)];
            float2 W = z[fpos(2048 - k)];
            const float sc = 0.5f / 2048.0f;
            float hr = (Z.x + W.x) * sc, hi = (Z.y - W.y) * sc;
            float sr = (Z.y + W.y) * sc, si = (W.x - Z.x) * sc;
            float pr = hr * sr + hi * si;
            float pi = hi * sr - hr * si;
            if (k >= 32) {
                float a  = 4.0f * (hr * hr + hi * hi);
                float cm = 4.0f * sqrtf(pr * pr + pi * pi);
                xv[k - 32]        = a;
                xv[1024 + k - 32] = cm;
            }
            Gk[it] = make_float2(pr, pi);
        }
        __syncthreads();                         // all reads of z done
#pragma unroll
        for (int it = 0; it < 4; it++) {
            int k = 1 + tid + it * 256;
            z[k] = make_float2(Gk[it].x, -Gk[it].y);
            if (k < 1024) z[2048 - k] = Gk[it];  // k=1024 self-paired (pi=0)
        }
        if (tid == 0) z[0] = make_float2(0.f, 0.f);  // Yc[0] = 0
        __syncthreads();
    }

    // ---- 5. FFT #2 (correlation) ----------------------------------------
    fft2048(z, tid);

    // ---- 6. circular->linear corrections, Pearson corr, max -------------
    if (tid < 128) {
        float corr = -2.f;
        if (tid < 103) {
            int d = tid - 51;                     // shift
            float rc = 2048.0f * z[fpos(d & 2047)].x;
            float wrap = 0.f;
            if (d >= 0) {
                for (int t = 0; t < d; t++) wrap += xh[t] * yc[2048 - d + t];
            } else {
                int m = -d;
                for (int t = 0; t < m; t++) wrap += xh[2048 - m + t] * yc[t];
            }
            float acc = rc - wrap;
            float S1, S2v;
            if (d >= 0) { S1 = s_T1 - P1[d];  S2v = s_T2 - P2[d]; }
            else        { S1 = s_T1 - Q1[-d]; S2v = s_T2 - Q2[-d]; }
            float varx = S2v - S1 * S1 * (1.0f / 2048.0f);
            corr = acc / sqrtf(varx * s_Vy);
        }
        for (int o = 16; o; o >>= 1)
            corr = fmaxf(corr, __shfl_xor_sync(0xffffffffu, corr, o));
        if (lane == 0) wmax[wid] = corr;
    }
    __syncthreads();
    if (tid == 0) {
        float b = fmaxf(fmaxf(wmax[0], wmax[1]), fmaxf(wmax[2], wmax[3]));
        s_lossbase = (1.0f - b) / (1.0f + b);
    }

    // ---- 7. dual parallel inclusive scan over 993 elements --------------
    {
        const int i0 = tid * 4;
        float av[4], bv[4];
#pragma unroll
        for (int u = 0; u < 4; u++) {
            int i = i0 + u;
            av[u] = (i < 993) ? xv[i] : 0.f;
            bv[u] = (i < 993) ? xv[1024 + i] : 0.f;
        }
        av[1] += av[0]; av[2] += av[1]; av[3] += av[2];
        bv[1] += bv[0]; bv[2] += bv[1]; bv[3] += bv[2];
        float la = av[3], lb = bv[3];
        float ainc = la, binc = lb;
#pragma unroll
        for (int o = 1; o < 32; o <<= 1) {
            float va = __shfl_up_sync(0xffffffffu, ainc, o);
            float vb = __shfl_up_sync(0xffffffffu, binc, o);
            if (lane >= o) { ainc += va; binc += vb; }
        }
        if (lane == 31) { wA[wid] = ainc; wB[wid] = binc; }
        __syncthreads();
        float baseA = 0.f, baseB = 0.f;
        for (int w = 0; w < wid; w++) { baseA += wA[w]; baseB += wB[w]; }
        float aex = baseA + ainc - la;
        float bex = baseB + binc - lb;
#pragma unroll
        for (int u = 0; u < 4; u++) {
            int i = i0 + u;
            if (i < 993) {
                xv[i]        = aex + av[u];
                xv[1024 + i] = bex + bv[u];
            }
        }
        __syncthreads();
        if (tid == 0) {
            float tot = xv[992];
            s_total   = tot;
            s_inv     = 1.0f / sqrtf(tot);
            s_tot2raw = xv[1024 + 992];
        }
        __syncthreads();
    }

    // ---- 8. edges: searchsorted(si, k/16*total, 'right'), clip ----------
    if (tid < 17) {
        float v = ((float)tid * (1.0f / 16.0f)) * s_total;
        int lo = 0, hi = 993;
        while (lo < hi) {
            int mid = (lo + hi) >> 1;
            if (xv[mid] <= v) lo = mid + 1; else hi = mid;
        }
        if (lo > 992) lo = 992;
        s_edges[tid] = lo;
    }
    __syncthreads();

    // ---- 9. chisq + final loss ------------------------------------------
    if (tid == 0) {
        float inv = s_inv;
        float total2 = s_tot2raw * inv;
        float mean = total2 * (1.0f / 16.0f);
        float ssum = 0.f;
        for (int k = 0; k < 16; k++) {
            float r = xv[1024 + s_edges[k + 1]] * inv;
            float l = xv[1024 + s_edges[k]] * inv;
            float d = (r - l) - mean;
            ssum += d * d;
        }
        float chisq = 16.0f * ssum * (1.0f / 15.0f);
        float c3 = chisq * chisq * chisq;
        out[row] = s_lossbase * powf(1.0f + c3, 1.0f / 6.0f);
    }
}

extern "C" void kernel_launch(void* const* d_in, const int* in_sizes, int n_in,
                              void* d_out, int out_size)
{
    const float* x_hat = (const float*)d_in[0];
    const float* x     = (const float*)d_in[1];
    float* out = (float*)d_out;
    tw_init_kernel<<<8, 256>>>();
    mfl_kernel<<<512, 256>>>(x_hat, x, out);
}

// round 4
// speedup vs baseline: 2.8241x; 1.3022x over previous
#include <cuda_runtime.h>
#include <math.h>

// MatchedFilterLoss fused kernel for GB300 (sm_103a)
// 512 blocks (one per batch*channel row) x 256 threads.
// Pearson computed spectrally (shared with chisq's H*conj(S) product).
// z[] accesses go through an XOR bank swizzle that makes every FFT stage,
// the digit-reversed untangle reads, and the Hermitian writes conflict-free.

#define NTH 256

__device__ float2 d_tw[2048];   // w_2048^t = exp(-2*pi*i*t/2048)

__global__ void tw_init_kernel()
{
    int t = blockIdx.x * blockDim.x + threadIdx.x;
    if (t < 2048) {
        float s, c;
        sincospif(-(float)t * (1.0f / 1024.0f), &s, &c);
        d_tw[t] = make_float2(c, s);
    }
}

// storage position of natural frequency k after radix-[4,4,4,4,4,2] DIF
__device__ __forceinline__ int fpos(int k)
{
    return ((k & 3) << 9) | (((k >> 2) & 3) << 7) | (((k >> 4) & 3) << 5)
         | (((k >> 6) & 3) << 3) | (((k >> 8) & 3) << 1) | (k >> 10);
}

// bank swizzle for float2 array z: injects high address bits into the low 4
// (bank-pair) bits so that every access pattern in this kernel has exactly
// 2 lanes per bank pair (the 8B-access minimum).
__device__ __forceinline__ int zsw(int p)
{
    return p ^ (((p >> 4) ^ (p >> 8)) & 15) ^ ((p >> 2) & 8);
}

__device__ __forceinline__ float2 cmul(float ar, float ai, float2 w)
{
    return make_float2(ar * w.x - ai * w.y, ar * w.y + ai * w.x);
}

// in-place 2048-pt complex DIF FFT over swizzled z (natural logical in ->
// digit-reversed logical out). Ends with a __syncthreads().
__device__ __forceinline__ void fft2048(float2* z, int tid)
{
#pragma unroll
    for (int s = 0; s < 5; s++) {
        const int lq   = 9 - 2 * s;          // log2(q), q = n/4
        const int q    = 1 << lq;
        const int mult = 1 << (2 * s);       // 2048/n
#pragma unroll
        for (int it = 0; it < 2; it++) {
            int b    = tid + it * 256;       // 512 butterflies
            int j    = b & (q - 1);
            int base = ((b >> lq) << (lq + 2)) + j;
            int p0 = zsw(base), p1 = zsw(base + q);
            int p2 = zsw(base + 2 * q), p3 = zsw(base + 3 * q);
            float2 x0 = z[p0], x1 = z[p1];
            float2 x2 = z[p2], x3 = z[p3];
            float t0r = x0.x + x2.x, t0i = x0.y + x2.y;
            float t1r = x1.x + x3.x, t1i = x1.y + x3.y;
            float t2r = x0.x - x2.x, t2i = x0.y - x2.y;
            float t3r = x1.y - x3.y, t3i = x3.x - x1.x;   // -i*(x1-x3)
            z[p0] = make_float2(t0r + t1r, t0i + t1i);
            int e1 = j * mult;
            float2 w1 = __ldg(&d_tw[e1]);
            float2 w2 = __ldg(&d_tw[2 * e1]);
            float2 w3 = __ldg(&d_tw[3 * e1]);
            z[p1] = cmul(t2r + t3r, t2i + t3i, w1);
            z[p2] = cmul(t0r - t1r, t0i - t1i, w2);
            z[p3] = cmul(t2r - t3r, t2i - t3i, w3);
        }
        __syncthreads();
    }
#pragma unroll
    for (int it = 0; it < 4; it++) {
        int b = tid + it * 256;              // 1024 radix-2 pairs
        int pa = zsw(2 * b), pb = zsw(2 * b + 1);
        float2 a = z[pa], c = z[pb];
        z[pa] = make_float2(a.x + c.x, a.y + c.y);
        z[pb] = make_float2(a.x - c.x, a.y - c.y);
    }
    __syncthreads();
}

__global__ __launch_bounds__(256, 4)
void mfl_kernel(const float* __restrict__ xhat_g,
                const float* __restrict__ x_g,
                float* __restrict__ out)
{
    __shared__ float xh[2048];       // centered x_hat (alive until corr phase)
    __shared__ float xv[2048];       // x; after FFT#1: integrand planes a|cm
    __shared__ float yc[2048];       // x - mean (alive until corr phase)
    __shared__ float2 z[2048];       // FFT workspace (bank-swizzled)
    __shared__ float P1[52], P2[52], Q1[52], Q2[52];
    __shared__ float red[24];
    __shared__ float wA[8], wB[8];
    __shared__ float wmax[4];
    __shared__ float s_mn, s_mx, s_my, s_T1, s_T2, s_Vy, s_lossbase;
    __shared__ float s_total, s_tot2raw, s_inv;
    __shared__ int   s_edges[17];

    const int tid  = threadIdx.x;
    const int lane = tid & 31;
    const int wid  = tid >> 5;
    const int row  = blockIdx.x;

    const float4* xh4 = (const float4*)(xhat_g + (size_t)row * 2048);
    const float4* x4g = (const float4*)(x_g    + (size_t)row * 2048);

    // ---- 1. vector load + first-pass stats (min/max of xh, sum of x) ----
    {
        float mn = 1e30f, mx = -1e30f, sy = 0.f;
#pragma unroll
        for (int c = 0; c < 2; c++) {
            int i = tid + c * 256;               // float4 index
            float4 h = xh4[i];
            float4 v = x4g[i];
            ((float4*)xh)[i] = h;
            ((float4*)xv)[i] = v;
            mn = fminf(mn, fminf(fminf(h.x, h.y), fminf(h.z, h.w)));
            mx = fmaxf(mx, fmaxf(fmaxf(h.x, h.y), fmaxf(h.z, h.w)));
            sy += v.x + v.y + v.z + v.w;
        }
        for (int off = 16; off; off >>= 1) {
            mn = fminf(mn, __shfl_xor_sync(0xffffffffu, mn, off));
            mx = fmaxf(mx, __shfl_xor_sync(0xffffffffu, mx, off));
            sy += __shfl_xor_sync(0xffffffffu, sy, off);
        }
        if (lane == 0) { red[wid] = mn; red[8 + wid] = mx; red[16 + wid] = sy; }
        __syncthreads();
        if (tid == 0) {
            float a = red[0], b = red[8], c = red[16];
            for (int w = 1; w < 8; w++) {
                a = fminf(a, red[w]); b = fmaxf(b, red[8 + w]); c += red[16 + w];
            }
            s_mn = a; s_mx = b; s_my = c * (1.0f / 2048.0f);
        }
        __syncthreads();
    }

    // ---- 2. center xh, yc = x - mean, totals, head/tail prefix sums -----
    {
        float mn = s_mn, inv = 1.0f / (s_mx - s_mn), my = s_my;
        float t1 = 0.f, t2 = 0.f, vy = 0.f;
#pragma unroll
        for (int c = 0; c < 2; c++) {
            int i = tid + c * 256;
            float4 h = ((float4*)xh)[i];
            float4 v = ((float4*)xv)[i];
            h.x = 2.0f * (h.x - mn) * inv - 1.0f;
            h.y = 2.0f * (h.y - mn) * inv - 1.0f;
            h.z = 2.0f * (h.z - mn) * inv - 1.0f;
            h.w = 2.0f * (h.w - mn) * inv - 1.0f;
            float4 y = make_float4(v.x - my, v.y - my, v.z - my, v.w - my);
            ((float4*)xh)[i] = h;
            ((float4*)yc)[i] = y;
            t1 += h.x + h.y + h.z + h.w;
            t2 += h.x * h.x + h.y * h.y + h.z * h.z + h.w * h.w;
            vy += y.x * y.x + y.y * y.y + y.z * y.z + y.w * y.w;
        }
        for (int off = 16; off; off >>= 1) {
            t1 += __shfl_xor_sync(0xffffffffu, t1, off);
            t2 += __shfl_xor_sync(0xffffffffu, t2, off);
            vy += __shfl_xor_sync(0xffffffffu, vy, off);
        }
        if (lane == 0) { red[wid] = t1; red[8 + wid] = t2; red[16 + wid] = vy; }
        __syncthreads();

        // head / tail prefix sums of centered xh (window mean/var corrections)
        if (tid < 52) {
            float a = 0.f, b = 0.f;
            for (int j = 0; j < tid; j++) { float u = xh[j]; a += u; b += u * u; }
            P1[tid] = a; P2[tid] = b;
        } else if (tid >= 64 && tid < 116) {
            int m = tid - 64;
            float a = 0.f, b = 0.f;
            for (int j = 0; j < m; j++) { float u = xh[2047 - j]; a += u; b += u * u; }
            Q1[m] = a; Q2[m] = b;
        }
        if (tid == 128) {
            float a = red[0], b = red[8], c = red[16];
            for (int w = 1; w < 8; w++) { a += red[w]; b += red[8 + w]; c += red[16 + w]; }
            s_T1 = a; s_T2 = b; s_Vy = c;
        }

        // pack z = centered_xh + i * x (same sync covers it)
#pragma unroll
        for (int c = 0; c < 8; c++) {
            int i = tid + c * 256;
            z[zsw(i)] = make_float2(xh[i], xv[i]);
        }
        __syncthreads();
    }

    // ---- 3. FFT #1 ------------------------------------------------------
    fft2048(z, tid);

    // ---- 4. untangle all bins: chisq integrands + corr spectrum G -------
    // H = rfft(xh)/2048, S = rfft(x)/2048, P = H*conj(S).
    // G[k] = conj(P[k]) (k=1..1024), G[2048-k] = P[k], G[0]=0 (Hermitian).
    // Then r_circ[d] = 2048 * Re( FFT(G)[d] ).
    {
        float2 Gk[4];
#pragma unroll
        for (int it = 0; it < 4; it++) {
            int k = 1 + tid + it * 256;          // 1..1024
            float2 Z = z[zsw(fpos(k))];
            float2 W = z[zsw(fpos(2048 - k))];
            const float sc = 0.5f / 2048.0f;
            float hr = (Z.x + W.x) * sc, hi = (Z.y - W.y) * sc;
            float sr = (Z.y + W.y) * sc, si = (W.x - Z.x) * sc;
            float pr = hr * sr + hi * si;
            float pi = hi * sr - hr * si;
            if (k >= 32) {
                float a  = 4.0f * (hr * hr + hi * hi);
                float cm = 4.0f * sqrtf(pr * pr + pi * pi);
                xv[k - 32]        = a;
                xv[1024 + k - 32] = cm;
            }
            Gk[it] = make_float2(pr, pi);
        }
        __syncthreads();                         // all reads of z done
#pragma unroll
        for (int it = 0; it < 4; it++) {
            int k = 1 + tid + it * 256;
            z[zsw(k)] = make_float2(Gk[it].x, -Gk[it].y);
            if (k < 1024) z[zsw(2048 - k)] = Gk[it];  // k=1024 self-paired
        }
        if (tid == 0) z[zsw(0)] = make_float2(0.f, 0.f);
        __syncthreads();
    }

    // ---- 5. FFT #2 (correlation) ----------------------------------------
    fft2048(z, tid);

    // ---- 6. circular->linear corrections, Pearson corr, max -------------
    if (tid < 128) {
        float corr = -2.f;
        if (tid < 103) {
            int d = tid - 51;                     // shift
            float rc = 2048.0f * z[zsw(fpos(d & 2047))].x;
            float wrap = 0.f;
            if (d >= 0) {
                for (int t = 0; t < d; t++) wrap += xh[t] * yc[2048 - d + t];
            } else {
                int m = -d;
                for (int t = 0; t < m; t++) wrap += xh[2048 - m + t] * yc[t];
            }
            float acc = rc - wrap;
            float S1, S2v;
            if (d >= 0) { S1 = s_T1 - P1[d];  S2v = s_T2 - P2[d]; }
            else        { S1 = s_T1 - Q1[-d]; S2v = s_T2 - Q2[-d]; }
            float varx = S2v - S1 * S1 * (1.0f / 2048.0f);
            corr = acc / sqrtf(varx * s_Vy);
        }
        for (int o = 16; o; o >>= 1)
            corr = fmaxf(corr, __shfl_xor_sync(0xffffffffu, corr, o));
        if (lane == 0) wmax[wid] = corr;
    }
    __syncthreads();
    if (tid == 0) {
        float b = fmaxf(fmaxf(wmax[0], wmax[1]), fmaxf(wmax[2], wmax[3]));
        s_lossbase = (1.0f - b) / (1.0f + b);
    }

    // ---- 7. dual parallel inclusive scan over 993 elements --------------
    {
        const int i0 = tid * 4;
        float4 a4 = ((const float4*)xv)[tid];          // xv[i0..i0+3]
        float4 b4 = ((const float4*)xv)[256 + tid];    // xv[1024+i0..]
        float av[4] = { a4.x, a4.y, a4.z, a4.w };
        float bv[4] = { b4.x, b4.y, b4.z, b4.w };
#pragma unroll
        for (int u = 0; u < 4; u++) {
            if (i0 + u >= 993) { av[u] = 0.f; bv[u] = 0.f; }
        }
        av[1] += av[0]; av[2] += av[1]; av[3] += av[2];
        bv[1] += bv[0]; bv[2] += bv[1]; bv[3] += bv[2];
        float la = av[3], lb = bv[3];
        float ainc = la, binc = lb;
#pragma unroll
        for (int o = 1; o < 32; o <<= 1) {
            float va = __shfl_up_sync(0xffffffffu, ainc, o);
            float vb = __shfl_up_sync(0xffffffffu, binc, o);
            if (lane >= o) { ainc += va; binc += vb; }
        }
        if (lane == 31) { wA[wid] = ainc; wB[wid] = binc; }
        __syncthreads();
        float baseA = 0.f, baseB = 0.f;
        for (int w = 0; w < wid; w++) { baseA += wA[w]; baseB += wB[w]; }
        float aex = baseA + ainc - la;
        float bex = baseB + binc - lb;
        if (i0 + 3 < 993) {
            ((float4*)xv)[tid] =
                make_float4(aex + av[0], aex + av[1], aex + av[2], aex + av[3]);
            ((float4*)xv)[256 + tid] =
                make_float4(bex + bv[0], bex + bv[1], bex + bv[2], bex + bv[3]);
        } else {
#pragma unroll
            for (int u = 0; u < 4; u++) {
                int i = i0 + u;
                if (i < 993) {
                    xv[i]        = aex + av[u];
                    xv[1024 + i] = bex + bv[u];
                }
            }
        }
        __syncthreads();
        if (tid == 0) {
            float tot = xv[992];
            s_total   = tot;
            s_inv     = 1.0f / sqrtf(tot);
            s_tot2raw = xv[1024 + 992];
        }
        __syncthreads();
    }

    // ---- 8. edges: searchsorted(si, k/16*total, 'right'), clip ----------
    if (tid < 17) {
        float v = ((float)tid * (1.0f / 16.0f)) * s_total;
        int lo = 0, hi = 993;
        while (lo < hi) {
            int mid = (lo + hi) >> 1;
            if (xv[mid] <= v) lo = mid + 1; else hi = mid;
        }
        if (lo > 992) lo = 992;
        s_edges[tid] = lo;
    }
    __syncthreads();

    // ---- 9. chisq + final loss ------------------------------------------
    if (tid == 0) {
        float inv = s_inv;
        float total2 = s_tot2raw * inv;
        float mean = total2 * (1.0f / 16.0f);
        float ssum = 0.f;
        for (int k = 0; k < 16; k++) {
            float r = xv[1024 + s_edges[k + 1]] * inv;
            float l = xv[1024 + s_edges[k]] * inv;
            float d = (r - l) - mean;
            ssum += d * d;
        }
        float chisq = 16.0f * ssum * (1.0f / 15.0f);
        float c3 = chisq * chisq * chisq;
        out[row] = s_lossbase * powf(1.0f + c3, 1.0f / 6.0f);
    }
}

extern "C" void kernel_launch(void* const* d_in, const int* in_sizes, int n_in,
                              void* d_out, int out_size)
{
    const float* x_hat = (const float*)d_in[0];
    const float* x     = (const float*)d_in[1];
    float* out = (float*)d_out;
    tw_init_kernel<<<8, 256>>>();
    mfl_kernel<<<512, 256>>>(x_hat, x, out);
}

// round 5
// speedup vs baseline: 3.0240x; 1.0708x over previous
#include <cuda_runtime.h>
#include <math.h>

// MatchedFilterLoss fused kernel for GB300 (sm_103a)
// 512 blocks x 256 threads. Pearson computed spectrally.
// FFT: radix-8 x3 + radix-4, stage 1 fed from registers; z[] bank-swizzled.

#define NTH 256

__device__ float2 d_tw[2048];   // w_2048^t = exp(-2*pi*i*t/2048)

__global__ void tw_init_kernel()
{
    int t = blockIdx.x * blockDim.x + threadIdx.x;
    if (t < 2048) {
        float s, c;
        sincospif(-(float)t * (1.0f / 1024.0f), &s, &c);
        d_tw[t] = make_float2(c, s);
    }
}

// storage position of natural frequency k after radix-[8,8,8,4] DIF
__device__ __forceinline__ int fpos8(int k)
{
    return ((k & 7) << 8) | (((k >> 3) & 7) << 5) | (((k >> 6) & 7) << 2) | (k >> 9);
}

// bank swizzle for float2 array z: 2 lanes per bank pair (8B minimum) for all
// access patterns in this kernel (strides 256/32/4/1, fpos8 reads, Hermitian).
__device__ __forceinline__ int zs(int p)
{
    return p ^ ((p >> 4) & 15) ^ ((p >> 8) & 7) ^ (((p >> 6) & 1) << 3);
}

__device__ __forceinline__ float2 c_add(float2 a, float2 b){ return make_float2(a.x+b.x, a.y+b.y); }
__device__ __forceinline__ float2 c_sub(float2 a, float2 b){ return make_float2(a.x-b.x, a.y-b.y); }
__device__ __forceinline__ float2 cmul2(float2 a, float2 w)
{
    return make_float2(a.x*w.x - a.y*w.y, a.x*w.y + a.y*w.x);
}

// radix-8 DIF butterfly: x[r] <- A_r = sum_s x_s * w8^{rs}
__device__ __forceinline__ void radix8_core(float2* x)
{
    const float H = 0.70710678118654752f;
    float2 a0=c_add(x[0],x[4]), d0=c_sub(x[0],x[4]);
    float2 a1=c_add(x[1],x[5]), d1=c_sub(x[1],x[5]);
    float2 a2=c_add(x[2],x[6]), d2=c_sub(x[2],x[6]);
    float2 a3=c_add(x[3],x[7]), d3=c_sub(x[3],x[7]);
    float2 b0=d0;
    float2 b1=make_float2(H*(d1.x+d1.y), H*(d1.y-d1.x));     // * w8^1
    float2 b2=make_float2(d2.y, -d2.x);                       // * w8^2 = -i
    float2 b3=make_float2(H*(d3.y-d3.x), -H*(d3.x+d3.y));     // * w8^3
    // DFT4 on a -> A0,A2,A4,A6
    float2 t0=c_add(a0,a2), t1=c_add(a1,a3), t2=c_sub(a0,a2);
    float2 u =c_sub(a1,a3); float2 t3=make_float2(u.y,-u.x);
    x[0]=c_add(t0,t1); x[2]=c_add(t2,t3); x[4]=c_sub(t0,t1); x[6]=c_sub(t2,t3);
    // DFT4 on b -> A1,A3,A5,A7
    t0=c_add(b0,b2); t1=c_add(b1,b3); t2=c_sub(b0,b2);
    u=c_sub(b1,b3); t3=make_float2(u.y,-u.x);
    x[1]=c_add(t0,t1); x[3]=c_add(t2,t3); x[5]=c_sub(t0,t1); x[7]=c_sub(t2,t3);
}

// store radix-8 outputs with outer twiddles W^{j*r}, W-exponent step tm
__device__ __forceinline__ void bfly8_store(float2* z, const float2* x, int base, int q, int tm)
{
    z[zs(base)] = x[0];
#pragma unroll
    for (int r = 1; r < 8; r++) {
        float2 w = __ldg(&d_tw[tm * r]);
        z[zs(base + q * r)] = cmul2(x[r], w);
    }
}

// generic radix-8 stage reading from z; Q = n/8 (compile-time)
template<int Q>
__device__ __forceinline__ void stage8_z(float2* z, int tid)
{
    const int j    = tid & (Q - 1);
    const int base = (tid / Q) * (Q * 8) + j;
    float2 x[8];
#pragma unroll
    for (int s = 0; s < 8; s++) x[s] = z[zs(base + Q * s)];
    radix8_core(x);
    bfly8_store(z, x, base, Q, (256 / Q) * j);
}

// final radix-4 stage (q=1, j=0, no twiddles), natural order within quads
__device__ __forceinline__ void stage4_final(float2* z, int tid)
{
#pragma unroll
    for (int it = 0; it < 2; it++) {
        int base = 4 * (tid + it * 256);
        float2 y0=z[zs(base)], y1=z[zs(base+1)], y2=z[zs(base+2)], y3=z[zs(base+3)];
        float2 t0=c_add(y0,y2), t1=c_add(y1,y3), t2=c_sub(y0,y2);
        float2 u =c_sub(y1,y3); float2 t3=make_float2(u.y,-u.x);
        z[zs(base)]  =c_add(t0,t1); z[zs(base+1)]=c_add(t2,t3);
        z[zs(base+2)]=c_sub(t0,t1); z[zs(base+3)]=c_sub(t2,t3);
    }
}

__device__ __forceinline__ void fft_tail(float2* z, int tid)  // stages 2..4
{
    stage8_z<32>(z, tid); __syncthreads();
    stage8_z<4>(z, tid);  __syncthreads();
    stage4_final(z, tid); __syncthreads();
}

__global__ __launch_bounds__(256, 4)
void mfl_kernel(const float* __restrict__ xhat_g,
                const float* __restrict__ x_g,
                float* __restrict__ out)
{
    __shared__ float xh[2048];       // centered x_hat (P/Q prefix + wrap)
    __shared__ float yc[2048];       // raw x (wrap corrections)
    __shared__ float xv[2048];       // integrand planes a | cm, then cumsums
    __shared__ float2 z[2048];       // FFT workspace (bank-swizzled)
    __shared__ float P1[52], P2[52], Q1[52], Q2[52];
    __shared__ float red[24];
    __shared__ float wA[8], wB[8];
    __shared__ float wmax[4];
    __shared__ float s_mn, s_mx, s_my, s_T1, s_T2, s_Vy, s_lossbase;
    __shared__ float s_total, s_tot2raw, s_inv;
    __shared__ int   s_edges[17];

    const int tid  = threadIdx.x;
    const int lane = tid & 31;
    const int wid  = tid >> 5;
    const int row  = blockIdx.x;

    const float* xh_in = xhat_g + (size_t)row * 2048;
    const float* x_in  = x_g    + (size_t)row * 2048;

    // ---- 1. register-resident load (stride 256 = FFT stage-1 footprint) --
    float hr[8], xr[8];
#pragma unroll
    for (int s = 0; s < 8; s++) {
        hr[s] = xh_in[tid + 256 * s];
        xr[s] = x_in[tid + 256 * s];
    }
    {
        float mn = 1e30f, mx = -1e30f, sy = 0.f;
#pragma unroll
        for (int s = 0; s < 8; s++) {
            mn = fminf(mn, hr[s]); mx = fmaxf(mx, hr[s]); sy += xr[s];
        }
        for (int o = 16; o; o >>= 1) {
            mn = fminf(mn, __shfl_xor_sync(0xffffffffu, mn, o));
            mx = fmaxf(mx, __shfl_xor_sync(0xffffffffu, mx, o));
            sy += __shfl_xor_sync(0xffffffffu, sy, o);
        }
        if (lane == 0) { red[wid] = mn; red[8 + wid] = mx; red[16 + wid] = sy; }
        __syncthreads();
        if (tid == 0) {
            float a = red[0], b = red[8], c = red[16];
            for (int w = 1; w < 8; w++) {
                a = fminf(a, red[w]); b = fmaxf(b, red[8 + w]); c += red[16 + w];
            }
            s_mn = a; s_mx = b; s_my = c * (1.0f / 2048.0f);
        }
        __syncthreads();
    }

    // ---- 2. center in regs, write xh/yc, totals ------------------------
    {
        float mn = s_mn, inv = 1.0f / (s_mx - s_mn), my = s_my;
        float t1 = 0.f, t2 = 0.f, vy = 0.f;
#pragma unroll
        for (int s = 0; s < 8; s++) {
            float h = 2.0f * (hr[s] - mn) * inv - 1.0f;
            hr[s] = h;
            xh[tid + 256 * s] = h;
            yc[tid + 256 * s] = xr[s];
            float y = xr[s] - my;
            t1 += h; t2 += h * h; vy += y * y;
        }
        for (int o = 16; o; o >>= 1) {
            t1 += __shfl_xor_sync(0xffffffffu, t1, o);
            t2 += __shfl_xor_sync(0xffffffffu, t2, o);
            vy += __shfl_xor_sync(0xffffffffu, vy, o);
        }
        if (lane == 0) { red[wid] = t1; red[8 + wid] = t2; red[16 + wid] = vy; }
        __syncthreads();
    }

    // ---- 3. FFT#1 stage 1 from registers; P/Q prefixes; T combine -------
    {
        float2 x[8];
#pragma unroll
        for (int s = 0; s < 8; s++) x[s] = make_float2(hr[s], xr[s]);
        radix8_core(x);
        bfly8_store(z, x, tid, 256, tid);      // q=256, tm=j=tid

        if (tid < 52) {
            float a = 0.f, b = 0.f;
            for (int j = 0; j < tid; j++) { float u = xh[j]; a += u; b += u * u; }
            P1[tid] = a; P2[tid] = b;
        } else if (tid >= 64 && tid < 116) {
            int m = tid - 64;
            float a = 0.f, b = 0.f;
            for (int j = 0; j < m; j++) { float u = xh[2047 - j]; a += u; b += u * u; }
            Q1[m] = a; Q2[m] = b;
        } else if (tid == 128) {
            float a = red[0], b = red[8], c = red[16];
            for (int w = 1; w < 8; w++) { a += red[w]; b += red[8 + w]; c += red[16 + w]; }
            s_T1 = a; s_T2 = b; s_Vy = c;
        }
        __syncthreads();
    }
    fft_tail(z, tid);                           // stages 2..4 of FFT#1

    // ---- 4. untangle: chisq integrands + Hermitian corr spectrum G ------
    {
        float2 Gk[4];
#pragma unroll
        for (int it = 0; it < 4; it++) {
            int k = 1 + tid + it * 256;          // 1..1024
            float2 Z = z[zs(fpos8(k))];
            float2 W = z[zs(fpos8(2048 - k))];
            const float sc = 0.5f / 2048.0f;
            float h_r = (Z.x + W.x) * sc, h_i = (Z.y - W.y) * sc;
            float s_r = (Z.y + W.y) * sc, s_i = (W.x - Z.x) * sc;
            float pr = h_r * s_r + h_i * s_i;
            float pi = h_i * s_r - h_r * s_i;
            if (k >= 32) {
                float a  = 4.0f * (h_r * h_r + h_i * h_i);
                float cm = 4.0f * sqrtf(pr * pr + pi * pi);
                xv[k - 32]        = a;
                xv[1024 + k - 32] = cm;
            }
            Gk[it] = make_float2(pr, pi);
        }
        __syncthreads();
#pragma unroll
        for (int it = 0; it < 4; it++) {
            int k = 1 + tid + it * 256;
            z[zs(k)] = make_float2(Gk[it].x, -Gk[it].y);
            if (k < 1024) z[zs(2048 - k)] = Gk[it];
        }
        if (tid == 0) z[zs(0)] = make_float2(0.f, 0.f);
        __syncthreads();
    }

    // ---- 5. FFT#2 (correlation) -----------------------------------------
    stage8_z<256>(z, tid); __syncthreads();
    fft_tail(z, tid);

    // ---- 6. circular->linear corrections, Pearson corr, max -------------
    if (tid < 128) {
        float corr = -2.f;
        if (tid < 103) {
            int d = tid - 51;
            float rc = 2048.0f * z[zs(fpos8(d & 2047))].x;
            float my = s_my;
            float wrap = 0.f;
            if (d >= 0) {
                for (int t = 0; t < d; t++) wrap += xh[t] * (yc[2048 - d + t] - my);
            } else {
                int m = -d;
                for (int t = 0; t < m; t++) wrap += xh[2048 - m + t] * (yc[t] - my);
            }
            float acc = rc - wrap;
            float S1, S2v;
            if (d >= 0) { S1 = s_T1 - P1[d];  S2v = s_T2 - P2[d]; }
            else        { S1 = s_T1 - Q1[-d]; S2v = s_T2 - Q2[-d]; }
            float varx = S2v - S1 * S1 * (1.0f / 2048.0f);
            corr = acc / sqrtf(varx * s_Vy);
        }
        for (int o = 16; o; o >>= 1)
            corr = fmaxf(corr, __shfl_xor_sync(0xffffffffu, corr, o));
        if (lane == 0) wmax[wid] = corr;
    }
    __syncthreads();
    if (tid == 0) {
        float b = fmaxf(fmaxf(wmax[0], wmax[1]), fmaxf(wmax[2], wmax[3]));
        s_lossbase = (1.0f - b) / (1.0f + b);
    }

    // ---- 7. dual parallel inclusive scan over 993 elements --------------
    {
        const int i0 = tid * 4;
        float4 a4 = ((const float4*)xv)[tid];
        float4 b4 = ((const float4*)xv)[256 + tid];
        float av[4] = { a4.x, a4.y, a4.z, a4.w };
        float bv[4] = { b4.x, b4.y, b4.z, b4.w };
#pragma unroll
        for (int u = 0; u < 4; u++) {
            if (i0 + u >= 993) { av[u] = 0.f; bv[u] = 0.f; }
        }
        av[1] += av[0]; av[2] += av[1]; av[3] += av[2];
        bv[1] += bv[0]; bv[2] += bv[1]; bv[3] += bv[2];
        float la = av[3], lb = bv[3];
        float ainc = la, binc = lb;
#pragma unroll
        for (int o = 1; o < 32; o <<= 1) {
            float va = __shfl_up_sync(0xffffffffu, ainc, o);
            float vb = __shfl_up_sync(0xffffffffu, binc, o);
            if (lane >= o) { ainc += va; binc += vb; }
        }
        if (lane == 31) { wA[wid] = ainc; wB[wid] = binc; }
        __syncthreads();
        float baseA = 0.f, baseB = 0.f;
        for (int w = 0; w < wid; w++) { baseA += wA[w]; baseB += wB[w]; }
        float aex = baseA + ainc - la;
        float bex = baseB + binc - lb;
        if (i0 + 3 < 993) {
            ((float4*)xv)[tid] =
                make_float4(aex + av[0], aex + av[1], aex + av[2], aex + av[3]);
            ((float4*)xv)[256 + tid] =
                make_float4(bex + bv[0], bex + bv[1], bex + bv[2], bex + bv[3]);
        } else {
#pragma unroll
            for (int u = 0; u < 4; u++) {
                int i = i0 + u;
                if (i < 993) {
                    xv[i]        = aex + av[u];
                    xv[1024 + i] = bex + bv[u];
                }
            }
        }
        __syncthreads();
        if (tid == 0) {
            float tot = xv[992];
            s_total   = tot;
            s_inv     = 1.0f / sqrtf(tot);
            s_tot2raw = xv[1024 + 992];
        }
        __syncthreads();
    }

    // ---- 8. edges: searchsorted(si, k/16*total, 'right'), clip ----------
    if (tid < 17) {
        float v = ((float)tid * (1.0f / 16.0f)) * s_total;
        int lo = 0, hi = 993;
        while (lo < hi) {
            int mid = (lo + hi) >> 1;
            if (xv[mid] <= v) lo = mid + 1; else hi = mid;
        }
        if (lo > 992) lo = 992;
        s_edges[tid] = lo;
    }
    __syncthreads();

    // ---- 9. chisq + final loss ------------------------------------------
    if (tid == 0) {
        float inv = s_inv;
        float total2 = s_tot2raw * inv;
        float mean = total2 * (1.0f / 16.0f);
        float ssum = 0.f;
        for (int k = 0; k < 16; k++) {
            float r = xv[1024 + s_edges[k + 1]] * inv;
            float l = xv[1024 + s_edges[k]] * inv;
            float d = (r - l) - mean;
            ssum += d * d;
        }
        float chisq = 16.0f * ssum * (1.0f / 15.0f);
        float c3 = chisq * chisq * chisq;
        out[row] = s_lossbase * powf(1.0f + c3, 1.0f / 6.0f);
    }
}

extern "C" void kernel_launch(void* const* d_in, const int* in_sizes, int n_in,
                              void* d_out, int out_size)
{
    const float* x_hat = (const float*)d_in[0];
    const float* x     = (const float*)d_in[1];
    float* out = (float*)d_out;
    tw_init_kernel<<<8, 256>>>();
    mfl_kernel<<<512, 256>>>(x_hat, x, out);
}

// round 6
// speedup vs baseline: 4.0474x; 1.3384x over previous
#include <cuda_runtime.h>
#include <math.h>

// MatchedFilterLoss fused kernel for GB300 (sm_103a)
// 512 blocks x 256 threads. Pearson computed spectrally.
// FFT: radix-8 x3 + radix-4; stage-1 fed from registers; z[] bank-swizzled;
// twiddles: ONE register-resident w1 per stage per thread, w2..w7 chained
// by complex multiplies (eliminates all steady-state twiddle L1 traffic).

#define NTH 256

__device__ float2 d_tw[2048];   // w_2048^t = exp(-2*pi*i*t/2048)

__global__ void tw_init_kernel()
{
    int t = blockIdx.x * blockDim.x + threadIdx.x;
    if (t < 2048) {
        float s, c;
        sincospif(-(float)t * (1.0f / 1024.0f), &s, &c);
        d_tw[t] = make_float2(c, s);
    }
}

// storage position of natural frequency k after radix-[8,8,8,4] DIF
__device__ __forceinline__ int fpos8(int k)
{
    return ((k & 7) << 8) | (((k >> 3) & 7) << 5) | (((k >> 6) & 7) << 2) | (k >> 9);
}

// bank swizzle for float2 array z: 2 lanes per bank pair (8B minimum) for all
// access patterns in this kernel (strides 256/32/4/1, fpos8 reads, Hermitian).
__device__ __forceinline__ int zs(int p)
{
    return p ^ ((p >> 4) & 15) ^ ((p >> 8) & 7) ^ (((p >> 6) & 1) << 3);
}

__device__ __forceinline__ float2 c_add(float2 a, float2 b){ return make_float2(a.x+b.x, a.y+b.y); }
__device__ __forceinline__ float2 c_sub(float2 a, float2 b){ return make_float2(a.x-b.x, a.y-b.y); }
__device__ __forceinline__ float2 cmul2(float2 a, float2 w)
{
    return make_float2(a.x*w.x - a.y*w.y, a.x*w.y + a.y*w.x);
}

// radix-8 DIF butterfly: x[r] <- A_r = sum_s x_s * w8^{rs}
__device__ __forceinline__ void radix8_core(float2* x)
{
    const float H = 0.70710678118654752f;
    float2 a0=c_add(x[0],x[4]), d0=c_sub(x[0],x[4]);
    float2 a1=c_add(x[1],x[5]), d1=c_sub(x[1],x[5]);
    float2 a2=c_add(x[2],x[6]), d2=c_sub(x[2],x[6]);
    float2 a3=c_add(x[3],x[7]), d3=c_sub(x[3],x[7]);
    float2 b0=d0;
    float2 b1=make_float2(H*(d1.x+d1.y), H*(d1.y-d1.x));     // * w8^1
    float2 b2=make_float2(d2.y, -d2.x);                       // * w8^2 = -i
    float2 b3=make_float2(H*(d3.y-d3.x), -H*(d3.x+d3.y));     // * w8^3
    // DFT4 on a -> A0,A2,A4,A6
    float2 t0=c_add(a0,a2), t1=c_add(a1,a3), t2=c_sub(a0,a2);
    float2 u =c_sub(a1,a3); float2 t3=make_float2(u.y,-u.x);
    x[0]=c_add(t0,t1); x[2]=c_add(t2,t3); x[4]=c_sub(t0,t1); x[6]=c_sub(t2,t3);
    // DFT4 on b -> A1,A3,A5,A7
    t0=c_add(b0,b2); t1=c_add(b1,b3); t2=c_sub(b0,b2);
    u=c_sub(b1,b3); t3=make_float2(u.y,-u.x);
    x[1]=c_add(t0,t1); x[3]=c_add(t2,t3); x[5]=c_sub(t0,t1); x[7]=c_sub(t2,t3);
}

// store radix-8 outputs; outer twiddles w^r chained from register w1
__device__ __forceinline__ void bfly8_store(float2* z, const float2* x, int base, int q, float2 w1)
{
    float2 w2 = cmul2(w1, w1);
    float2 w3 = cmul2(w2, w1);
    float2 w4 = cmul2(w2, w2);
    float2 w5 = cmul2(w2, w3);
    float2 w6 = cmul2(w3, w3);
    float2 w7 = cmul2(w3, w4);
    z[zs(base)]         = x[0];
    z[zs(base + q)]     = cmul2(x[1], w1);
    z[zs(base + 2*q)]   = cmul2(x[2], w2);
    z[zs(base + 3*q)]   = cmul2(x[3], w3);
    z[zs(base + 4*q)]   = cmul2(x[4], w4);
    z[zs(base + 5*q)]   = cmul2(x[5], w5);
    z[zs(base + 6*q)]   = cmul2(x[6], w6);
    z[zs(base + 7*q)]   = cmul2(x[7], w7);
}

// generic radix-8 stage reading from z; Q = n/8 (compile-time); w1 in register
template<int Q>
__device__ __forceinline__ void stage8_z(float2* z, int tid, float2 w1)
{
    const int j    = tid & (Q - 1);
    const int base = (tid / Q) * (Q * 8) + j;
    float2 x[8];
#pragma unroll
    for (int s = 0; s < 8; s++) x[s] = z[zs(base + Q * s)];
    radix8_core(x);
    bfly8_store(z, x, base, Q, w1);
}

// final radix-4 stage (q=1, j=0, no twiddles)
__device__ __forceinline__ void stage4_final(float2* z, int tid)
{
#pragma unroll
    for (int it = 0; it < 2; it++) {
        int base = 4 * (tid + it * 256);
        float2 y0=z[zs(base)], y1=z[zs(base+1)], y2=z[zs(base+2)], y3=z[zs(base+3)];
        float2 t0=c_add(y0,y2), t1=c_add(y1,y3), t2=c_sub(y0,y2);
        float2 u =c_sub(y1,y3); float2 t3=make_float2(u.y,-u.x);
        z[zs(base)]  =c_add(t0,t1); z[zs(base+1)]=c_add(t2,t3);
        z[zs(base+2)]=c_sub(t0,t1); z[zs(base+3)]=c_sub(t2,t3);
    }
}

// stages 2..4 (twiddle registers for Q=32 and Q=4 passed in)
__device__ __forceinline__ void fft_tail(float2* z, int tid, float2 twB, float2 twC)
{
    stage8_z<32>(z, tid, twB); __syncthreads();
    stage8_z<4>(z, tid, twC);  __syncthreads();
    stage4_final(z, tid);      __syncthreads();
}

__global__ __launch_bounds__(256, 4)
void mfl_kernel(const float* __restrict__ xhat_g,
                const float* __restrict__ x_g,
                float* __restrict__ out)
{
    __shared__ float xh[2048];       // centered x_hat (P/Q prefix + wrap)
    __shared__ float yc[2048];       // raw x (wrap corrections)
    __shared__ float xv[2048];       // integrand planes a | cm, then cumsums
    __shared__ float2 z[2048];       // FFT workspace (bank-swizzled)
    __shared__ float P1[52], P2[52], Q1[52], Q2[52];
    __shared__ float red[24];
    __shared__ float wA[8], wB[8];
    __shared__ float wmax[4];
    __shared__ float s_mn, s_mx, s_my, s_T1, s_T2, s_Vy, s_lossbase;
    __shared__ float s_total, s_tot2raw, s_inv;
    __shared__ int   s_edges[17];

    const int tid  = threadIdx.x;
    const int lane = tid & 31;
    const int wid  = tid >> 5;
    const int row  = blockIdx.x;

    const float* xh_in = xhat_g + (size_t)row * 2048;
    const float* x_in  = x_g    + (size_t)row * 2048;

    // per-thread stage-1 twiddles, loaded ONCE, reused by both FFTs
    float2 twA = __ldg(&d_tw[tid]);              // Q=256 stage: tm = tid
    float2 twB = __ldg(&d_tw[8 * (tid & 31)]);   // Q=32 stage:  tm = 8j
    float2 twC = __ldg(&d_tw[64 * (tid & 3)]);   // Q=4 stage:   tm = 64j

    // ---- 1. register-resident load (stride 256 = FFT stage-1 footprint) --
    float hr[8], xr[8];
#pragma unroll
    for (int s = 0; s < 8; s++) {
        hr[s] = xh_in[tid + 256 * s];
        xr[s] = x_in[tid + 256 * s];
    }
    {
        float mn = 1e30f, mx = -1e30f, sy = 0.f;
#pragma unroll
        for (int s = 0; s < 8; s++) {
            mn = fminf(mn, hr[s]); mx = fmaxf(mx, hr[s]); sy += xr[s];
        }
        for (int o = 16; o; o >>= 1) {
            mn = fminf(mn, __shfl_xor_sync(0xffffffffu, mn, o));
            mx = fmaxf(mx, __shfl_xor_sync(0xffffffffu, mx, o));
            sy += __shfl_xor_sync(0xffffffffu, sy, o);
        }
        if (lane == 0) { red[wid] = mn; red[8 + wid] = mx; red[16 + wid] = sy; }
        __syncthreads();
        if (tid == 0) {
            float a = red[0], b = red[8], c = red[16];
            for (int w = 1; w < 8; w++) {
                a = fminf(a, red[w]); b = fmaxf(b, red[8 + w]); c += red[16 + w];
            }
            s_mn = a; s_mx = b; s_my = c * (1.0f / 2048.0f);
        }
        __syncthreads();
    }

    // ---- 2. center in regs, write xh/yc, totals ------------------------
    {
        float mn = s_mn, inv = 1.0f / (s_mx - s_mn), my = s_my;
        float t1 = 0.f, t2 = 0.f, vy = 0.f;
#pragma unroll
        for (int s = 0; s < 8; s++) {
            float h = 2.0f * (hr[s] - mn) * inv - 1.0f;
            hr[s] = h;
            xh[tid + 256 * s] = h;
            yc[tid + 256 * s] = xr[s];
            float y = xr[s] - my;
            t1 += h; t2 += h * h; vy += y * y;
        }
        for (int o = 16; o; o >>= 1) {
            t1 += __shfl_xor_sync(0xffffffffu, t1, o);
            t2 += __shfl_xor_sync(0xffffffffu, t2, o);
            vy += __shfl_xor_sync(0xffffffffu, vy, o);
        }
        if (lane == 0) { red[wid] = t1; red[8 + wid] = t2; red[16 + wid] = vy; }
        __syncthreads();
    }

    // ---- 3. FFT#1 stage 1 from registers; P/Q prefixes; T combine -------
    {
        float2 x[8];
#pragma unroll
        for (int s = 0; s < 8; s++) x[s] = make_float2(hr[s], xr[s]);
        radix8_core(x);
        bfly8_store(z, x, tid, 256, twA);       // q=256, tm=tid

        if (tid < 52) {
            float a = 0.f, b = 0.f;
            for (int j = 0; j < tid; j++) { float u = xh[j]; a += u; b += u * u; }
            P1[tid] = a; P2[tid] = b;
        } else if (tid >= 64 && tid < 116) {
            int m = tid - 64;
            float a = 0.f, b = 0.f;
            for (int j = 0; j < m; j++) { float u = xh[2047 - j]; a += u; b += u * u; }
            Q1[m] = a; Q2[m] = b;
        } else if (tid == 128) {
            float a = red[0], b = red[8], c = red[16];
            for (int w = 1; w < 8; w++) { a += red[w]; b += red[8 + w]; c += red[16 + w]; }
            s_T1 = a; s_T2 = b; s_Vy = c;
        }
        __syncthreads();
    }
    fft_tail(z, tid, twB, twC);                 // stages 2..4 of FFT#1

    // ---- 4. untangle: chisq integrands + Hermitian corr spectrum G ------
    {
        float2 Gk[4];
#pragma unroll
        for (int it = 0; it < 4; it++) {
            int k = 1 + tid + it * 256;          // 1..1024
            float2 Z = z[zs(fpos8(k))];
            float2 W = z[zs(fpos8(2048 - k))];
            const float sc = 0.5f / 2048.0f;
            float h_r = (Z.x + W.x) * sc, h_i = (Z.y - W.y) * sc;
            float s_r = (Z.y + W.y) * sc, s_i = (W.x - Z.x) * sc;
            float pr = h_r * s_r + h_i * s_i;
            float pi = h_i * s_r - h_r * s_i;
            if (k >= 32) {
                float a  = 4.0f * (h_r * h_r + h_i * h_i);
                float cm = 4.0f * sqrtf(pr * pr + pi * pi);
                xv[k - 32]        = a;
                xv[1024 + k - 32] = cm;
            }
            Gk[it] = make_float2(pr, pi);
        }
        __syncthreads();
#pragma unroll
        for (int it = 0; it < 4; it++) {
            int k = 1 + tid + it * 256;
            z[zs(k)] = make_float2(Gk[it].x, -Gk[it].y);
            if (k < 1024) z[zs(2048 - k)] = Gk[it];
        }
        if (tid == 0) z[zs(0)] = make_float2(0.f, 0.f);
        __syncthreads();
    }

    // ---- 5. FFT#2 (correlation) -----------------------------------------
    stage8_z<256>(z, tid, twA); __syncthreads();
    fft_tail(z, tid, twB, twC);

    // ---- 6. circular->linear corrections, Pearson corr, max -------------
    if (tid < 128) {
        float corr = -2.f;
        if (tid < 103) {
            int d = tid - 51;
            float rc = 2048.0f * z[zs(fpos8(d & 2047))].x;
            float my = s_my;
            float wrap = 0.f;
            if (d >= 0) {
                for (int t = 0; t < d; t++) wrap += xh[t] * (yc[2048 - d + t] - my);
            } else {
                int m = -d;
                for (int t = 0; t < m; t++) wrap += xh[2048 - m + t] * (yc[t] - my);
            }
            float acc = rc - wrap;
            float S1, S2v;
            if (d >= 0) { S1 = s_T1 - P1[d];  S2v = s_T2 - P2[d]; }
            else        { S1 = s_T1 - Q1[-d]; S2v = s_T2 - Q2[-d]; }
            float varx = S2v - S1 * S1 * (1.0f / 2048.0f);
            corr = acc / sqrtf(varx * s_Vy);
        }
        for (int o = 16; o; o >>= 1)
            corr = fmaxf(corr, __shfl_xor_sync(0xffffffffu, corr, o));
        if (lane == 0) wmax[wid] = corr;
    }
    __syncthreads();
    if (tid == 0) {
        float b = fmaxf(fmaxf(wmax[0], wmax[1]), fmaxf(wmax[2], wmax[3]));
        s_lossbase = (1.0f - b) / (1.0f + b);
    }

    // ---- 7. dual parallel inclusive scan over 993 elements --------------
    {
        const int i0 = tid * 4;
        float4 a4 = ((const float4*)xv)[tid];
        float4 b4 = ((const float4*)xv)[256 + tid];
        float av[4] = { a4.x, a4.y, a4.z, a4.w };
        float bv[4] = { b4.x, b4.y, b4.z, b4.w };
#pragma unroll
        for (int u = 0; u < 4; u++) {
            if (i0 + u >= 993) { av[u] = 0.f; bv[u] = 0.f; }
        }
        av[1] += av[0]; av[2] += av[1]; av[3] += av[2];
        bv[1] += bv[0]; bv[2] += bv[1]; bv[3] += bv[2];
        float la = av[3], lb = bv[3];
        float ainc = la, binc = lb;
#pragma unroll
        for (int o = 1; o < 32; o <<= 1) {
            float va = __shfl_up_sync(0xffffffffu, ainc, o);
            float vb = __shfl_up_sync(0xffffffffu, binc, o);
            if (lane >= o) { ainc += va; binc += vb; }
        }
        if (lane == 31) { wA[wid] = ainc; wB[wid] = binc; }
        __syncthreads();
        float baseA = 0.f, baseB = 0.f;
        for (int w = 0; w < wid; w++) { baseA += wA[w]; baseB += wB[w]; }
        float aex = baseA + ainc - la;
        float bex = baseB + binc - lb;
        if (i0 + 3 < 993) {
            ((float4*)xv)[tid] =
                make_float4(aex + av[0], aex + av[1], aex + av[2], aex + av[3]);
            ((float4*)xv)[256 + tid] =
                make_float4(bex + bv[0], bex + bv[1], bex + bv[2], bex + bv[3]);
        } else {
#pragma unroll
            for (int u = 0; u < 4; u++) {
                int i = i0 + u;
                if (i < 993) {
                    xv[i]        = aex + av[u];
                    xv[1024 + i] = bex + bv[u];
                }
            }
        }
        __syncthreads();
        if (tid == 0) {
            float tot = xv[992];
            s_total   = tot;
            s_inv     = 1.0f / sqrtf(tot);
            s_tot2raw = xv[1024 + 992];
        }
        __syncthreads();
    }

    // ---- 8. edges: searchsorted(si, k/16*total, 'right'), clip ----------
    if (tid < 17) {
        float v = ((float)tid * (1.0f / 16.0f)) * s_total;
        int lo = 0, hi = 993;
        while (lo < hi) {
            int mid = (lo + hi) >> 1;
            if (xv[mid] <= v) lo = mid + 1; else hi = mid;
        }
        if (lo > 992) lo = 992;
        s_edges[tid] = lo;
    }
    __syncthreads();

    // ---- 9. chisq + final loss ------------------------------------------
    if (tid == 0) {
        float inv = s_inv;
        float total2 = s_tot2raw * inv;
        float mean = total2 * (1.0f / 16.0f);
        float ssum = 0.f;
        for (int k = 0; k < 16; k++) {
            float r = xv[1024 + s_edges[k + 1]] * inv;
            float l = xv[1024 + s_edges[k]] * inv;
            float d = (r - l) - mean;
            ssum += d * d;
        }
        float chisq = 16.0f * ssum * (1.0f / 15.0f);
        float c3 = chisq * chisq * chisq;
        out[row] = s_lossbase * powf(1.0f + c3, 1.0f / 6.0f);
    }
}

extern "C" void kernel_launch(void* const* d_in, const int* in_sizes, int n_in,
                              void* d_out, int out_size)
{
    const float* x_hat = (const float*)d_in[0];
    const float* x     = (const float*)d_in[1];
    float* out = (float*)d_out;
    tw_init_kernel<<<8, 256>>>();
    mfl_kernel<<<512, 256>>>(x_hat, x, out);
}